// round 11
// baseline (speedup 1.0000x reference)
#include <cuda_runtime.h>
#include <cuda_fp16.h>
#include <cstdint>

#define B_  64
#define T_  256
#define C_  2048
#define HS_ 128
#define M_  (B_ * T_)

// Scratch (no cudaMalloc allowed)
__device__ __half g_k[M_ * HS_];
__device__ __half g_q[M_ * HS_];
__device__ __half g_v[M_ * HS_];
__device__ __half g_wh[3 * HS_ * C_];   // [384][2048] fp16 RNE, K-major
__device__ unsigned g_cnt[B_];          // per-batch proj-tile completion counters

__device__ __forceinline__ void cpa16(void* dst_smem, const void* src_gmem) {
    unsigned d = (unsigned)__cvta_generic_to_shared(dst_smem);
    asm volatile("cp.async.cg.shared.global [%0], [%1], 16;" :: "r"(d), "l"(src_gmem));
}
#define CP_COMMIT  asm volatile("cp.async.commit_group;")
#define CP_WAIT(n) asm volatile("cp.async.wait_group %0;" :: "n"(n))

#define MMA_F16(acc, a, b0, b1)                                                 \
    asm volatile(                                                               \
        "mma.sync.aligned.m16n8k16.row.col.f32.f16.f16.f32 "                    \
        "{%0,%1,%2,%3}, {%4,%5,%6,%7}, {%8,%9}, {%0,%1,%2,%3};"                 \
        : "+f"((acc)[0]), "+f"((acc)[1]), "+f"((acc)[2]), "+f"((acc)[3])        \
        : "r"((a)[0]), "r"((a)[1]), "r"((a)[2]), "r"((a)[3]),                   \
          "r"(b0), "r"(b1))

#define LDSM_X4(r0, r1, r2, r3, addr)                                           \
    asm volatile("ldmatrix.sync.aligned.m8n8.x4.shared.b16 {%0,%1,%2,%3}, [%4];"\
        : "=r"(r0), "=r"(r1), "=r"(r2), "=r"(r3) : "r"(addr))

#define LDSM_X4_T(r0, r1, r2, r3, addr)                                         \
    asm volatile("ldmatrix.sync.aligned.m8n8.x4.trans.shared.b16 {%0,%1,%2,%3}, [%4];"\
        : "=r"(r0), "=r"(r1), "=r"(r2), "=r"(r3) : "r"(addr))

// ----------------------------------------------------------------------------
// Prep: g_wh[p*128 + n][k] = fp16_rn(W_p[k][n]); also zeroes batch counters.
// ----------------------------------------------------------------------------
__global__ void prep_wt(const float* __restrict__ Wk, const float* __restrict__ Wq,
                        const float* __restrict__ Wv)
{
    if (blockIdx.x == 0 && blockIdx.y == 0 && blockIdx.z == 0 && threadIdx.x < B_)
        g_cnt[threadIdx.x] = 0;

    __shared__ float t[32][33];
    const float* W = blockIdx.z == 0 ? Wk : (blockIdx.z == 1 ? Wq : Wv);
    const int k0 = blockIdx.x * 32, n0 = blockIdx.y * 32;
    const int tx = threadIdx.x & 31, ty = threadIdx.x >> 5;
    #pragma unroll
    for (int i = 0; i < 32; i += 8)
        t[ty + i][tx] = W[(size_t)(k0 + ty + i) * HS_ + n0 + tx];
    __syncthreads();
    #pragma unroll
    for (int i = 0; i < 32; i += 8)
        g_wh[((size_t)blockIdx.z * HS_ + n0 + ty + i) * C_ + k0 + tx] =
            __float2half_rn(t[tx][ty + i]);
}

// ----------------------------------------------------------------------------
// Fused proj + attention mega-kernel.
// bids 0..255: proj m-tile (M64 x N384 x K2048), signals g_cnt[bid>>2] on done.
// bids 256..511: attention (bt = abid&3, b = abid>>2), spins until cnt[b]==4.
// smem = max(proj 101376, attn 96768) = 101376 -> 2 CTA/SM.
// ----------------------------------------------------------------------------
#define NF    384
#define NKT   (C_ / 32)          // 64
#define RSA   36                  // A row stride (floats)
#define ASTGF (64 * RSA)          // 9216 B per A stage
#define BSTGH (NF * 32)           // 24576 B per B stage
#define PSMEM (3 * (ASTGF * 4 + BSTGH * 2))   // 101376 B

__global__ __launch_bounds__(256, 2) void fused_kernel(const float* __restrict__ x,
                                                       float* __restrict__ out)
{
    extern __shared__ char smraw[];
    const int tid  = threadIdx.x;
    const int warp = tid >> 5, lane = tid & 31;
    const int lr = lane >> 2, lc = lane & 3;
    const int bid = blockIdx.x;

    if (bid < 256) {
        // ==================== PROJ path ====================
        float*  As = (float*)smraw;                        // 3 stages
        __half* Bs = (__half*)(smraw + 3 * ASTGF * 4);     // 3 stages, swizzled
        const uint32_t Bs_u = (uint32_t)__cvta_generic_to_shared(Bs);

        const int wm = warp >> 2, wn = warp & 3;           // 2m x 4n
        const int m0 = bid * 64;

        const int brow  = wn * 96 + (lane & 15);
        const int bsel  = (brow >> 1) & 3;
        const int bln16 = lane >> 4;

        auto load_tile = [&](int s, int j) {
            float*  Ad = As + s * ASTGF;
            __half* Bd = Bs + s * BSTGH;
            const int k0 = j * 32;
            #pragma unroll
            for (int i = 0; i < 2; i++) {                  // A: 512 x 16B
                int c = tid + i * 256, r = c >> 3, q = c & 7;
                cpa16(Ad + r * RSA + q * 4, x + (size_t)(m0 + r) * C_ + k0 + q * 4);
            }
            #pragma unroll
            for (int i = 0; i < 6; i++) {                  // B: 1536 x 16B, swizzled
                int c = tid + i * 256, r = c >> 2, cc = c & 3;
                cpa16(Bd + r * 32 + ((cc ^ ((r >> 1) & 3)) * 8),
                      g_wh + (size_t)r * C_ + k0 + cc * 8);
            }
            CP_COMMIT;
        };

        load_tile(0, 0);
        load_tile(1, 1);

        float acc[2][12][4] = {};

        for (int j = 0; j < NKT; j++) {
            if (j < NKT - 1) { CP_WAIT(1); } else { CP_WAIT(0); }
            __syncthreads();

            if (j + 2 < NKT) load_tile((j + 2) % 3, j + 2);

            const float*   Aj  = As + (j % 3) * ASTGF;
            const uint32_t Bju = Bs_u + (uint32_t)((j % 3) * BSTGH) * 2;

            #pragma unroll
            for (int ks = 0; ks < 2; ks++) {
                const int kb = ks * 16;
                unsigned a[2][4];
                #pragma unroll
                for (int mi = 0; mi < 2; mi++) {
                    const int row = wm * 32 + mi * 16 + lr;
                    float2 f0 = *(const float2*)(Aj + row * RSA + kb + 2 * lc);
                    float2 f1 = *(const float2*)(Aj + (row + 8) * RSA + kb + 2 * lc);
                    float2 f2 = *(const float2*)(Aj + row * RSA + kb + 2 * lc + 8);
                    float2 f3 = *(const float2*)(Aj + (row + 8) * RSA + kb + 2 * lc + 8);
                    __half2 h0 = __floats2half2_rn(f0.x, f0.y);
                    __half2 h1 = __floats2half2_rn(f1.x, f1.y);
                    __half2 h2 = __floats2half2_rn(f2.x, f2.y);
                    __half2 h3 = __floats2half2_rn(f3.x, f3.y);
                    a[mi][0] = *reinterpret_cast<unsigned*>(&h0);
                    a[mi][1] = *reinterpret_cast<unsigned*>(&h1);
                    a[mi][2] = *reinterpret_cast<unsigned*>(&h2);
                    a[mi][3] = *reinterpret_cast<unsigned*>(&h3);
                }
                const uint32_t chnk = (uint32_t)(((2 * ks + bln16) ^ bsel) * 16);
                #pragma unroll
                for (int pr = 0; pr < 6; pr++) {
                    unsigned b0, b1, b2, b3;
                    LDSM_X4(b0, b1, b2, b3,
                            Bju + (uint32_t)(brow * 64 + pr * 1024) + chnk);
                    MMA_F16(acc[0][2 * pr],     a[0], b0, b2);
                    MMA_F16(acc[0][2 * pr + 1], a[0], b1, b3);
                    MMA_F16(acc[1][2 * pr],     a[1], b0, b2);
                    MMA_F16(acc[1][2 * pr + 1], a[1], b1, b3);
                }
            }
        }

        // epilogue: fp16 outputs split across K/Q/V
        __half* const outp[3] = { g_k, g_q, g_v };
        #pragma unroll
        for (int mi = 0; mi < 2; mi++) {
            const int row0 = m0 + wm * 32 + mi * 16 + lr;
            #pragma unroll
            for (int ni = 0; ni < 12; ni++) {
                const int gcol = wn * 96 + ni * 8;
                __half* o = outp[gcol >> 7];
                const int col = (gcol & 127) + 2 * lc;
                __half2 h1 = __floats2half2_rn(acc[mi][ni][0], acc[mi][ni][1]);
                __half2 h2 = __floats2half2_rn(acc[mi][ni][2], acc[mi][ni][3]);
                *(__half2*)(o + (size_t)row0 * HS_ + col)       = h1;
                *(__half2*)(o + (size_t)(row0 + 8) * HS_ + col) = h2;
            }
        }

        // signal: this m-tile's batch has one more tile done
        __threadfence();
        __syncthreads();
        if (tid == 0) atomicAdd(&g_cnt[bid >> 2], 1u);

    } else {
        // ==================== ATTENTION path ====================
        const int abid = bid - 256;
        const int bt = abid & 3;
        const int b  = abid >> 2;

        // wait until all 4 proj m-tiles of batch b are complete
        if (tid == 0) {
            unsigned v;
            do {
                asm volatile("ld.global.acquire.gpu.b32 %0, [%1];"
                             : "=r"(v) : "l"(g_cnt + b) : "memory");
                if (v < 4) __nanosleep(128);
            } while (v < 4);
        }
        __syncthreads();

        float*  sc    = (float*)smraw;                 // [64][68]
        float*  f_row = sc + 64 * 68;                  // [64]
        float*  l_row = f_row + 64;                    // [64]
        __half* ph    = (__half*)(l_row + 64);         // [64][72]
        __half* kt    = ph + 64 * 72;                  // [64][136]
        __half* q0    = kt + 64 * 136;                 // [64][136]
        __half* q1    = q0 + 64 * 136;                 // [64][136]
        __half* vb    = q1 + 64 * 136;                 // [64][136]
        const uint32_t ph_u = (uint32_t)__cvta_generic_to_shared(ph);
        const uint32_t kt_u = (uint32_t)__cvta_generic_to_shared(kt);
        const uint32_t q0_u = (uint32_t)__cvta_generic_to_shared(q0);
        const uint32_t q1_u = (uint32_t)__cvta_generic_to_shared(q1);
        const uint32_t vb_u = (uint32_t)__cvta_generic_to_shared(vb);

        const int band = (warp & 3) * 16;
        const int hf = warp >> 2;
        const int t0 = bt * 64;
        const float scale = rsqrtf((float)C_);

        const uint32_t aK  = kt_u + (uint32_t)((band + (lane & 15)) * 136 + (lane >> 4) * 8) * 2;
        const uint32_t oQ  = (uint32_t)((hf * 32 + (lane & 7) + (lane >> 4) * 8) * 136
                                        + ((lane >> 3) & 1) * 8) * 2;
        const uint32_t aP  = ph_u + (uint32_t)((band + (lane & 15)) * 72 + (lane >> 4) * 8) * 2;
        const uint32_t bV  = vb_u + (uint32_t)(((lane & 7) + ((lane >> 3) & 1) * 8) * 136
                                               + hf * 64 + (lane >> 4) * 8) * 2;

        #pragma unroll
        for (int i = 0; i < 4; i++) {
            int c = tid + i * 256, r = c >> 4, q = c & 15;
            cpa16(kt + r * 136 + q * 8, g_k + (size_t)(b * T_ + t0 + r) * HS_ + q * 8);
            cpa16(q0 + r * 136 + q * 8, g_q + (size_t)(b * T_ + r) * HS_ + q * 8);
        }
        CP_COMMIT;
        CP_WAIT(0);
        __syncthreads();

        float m_r[8], l_r[8];
        float oacc[8][4] = {};
        #pragma unroll
        for (int i = 0; i < 8; i++) { m_r[i] = -INFINITY; l_r[i] = 0.f; }

        const int n_stiles = bt + 1;
        for (int st = 0; st < n_stiles; st++) {
            const int s0 = st * 64;
            __half* qn = (st & 1) ? q0 : q1;
            const uint32_t qc_u = (st & 1) ? q1_u : q0_u;

            if (st + 1 < n_stiles) {
                #pragma unroll
                for (int i = 0; i < 4; i++) {
                    int c = tid + i * 256, r = c >> 4, q = c & 15;
                    cpa16(qn + r * 136 + q * 8,
                          g_q + (size_t)(b * T_ + s0 + 64 + r) * HS_ + q * 8);
                }
            }
            CP_COMMIT;

            float sacc[4][4] = {};
            #pragma unroll
            for (int kk = 0; kk < 8; kk++) {
                unsigned a[4];
                LDSM_X4(a[0], a[1], a[2], a[3], aK + kk * 32);
                unsigned e0, e1, e2, e3, r0, r1, r2, r3;
                LDSM_X4(e0, e1, e2, e3, qc_u + oQ + kk * 32);
                LDSM_X4(r0, r1, r2, r3, qc_u + oQ + 16 * 136 * 2 + kk * 32);
                MMA_F16(sacc[0], a, e0, e1);
                MMA_F16(sacc[1], a, e2, e3);
                MMA_F16(sacc[2], a, r0, r1);
                MMA_F16(sacc[3], a, r2, r3);
            }
            const bool diag = (st == bt);
            #pragma unroll
            for (int nt = 0; nt < 4; nt++) {
                const int row = band + lr, col = hf * 32 + nt * 8 + 2 * lc;
                const int tg = t0 + row, sg = s0 + col;
                sc[row * 68 + col]           = (!diag || sg     <= tg)     ? sacc[nt][0] * scale : -INFINITY;
                sc[row * 68 + col + 1]       = (!diag || sg + 1 <= tg)     ? sacc[nt][1] * scale : -INFINITY;
                sc[(row + 8) * 68 + col]     = (!diag || sg     <= tg + 8) ? sacc[nt][2] * scale : -INFINITY;
                sc[(row + 8) * 68 + col + 1] = (!diag || sg + 1 <= tg + 8) ? sacc[nt][3] * scale : -INFINITY;
            }
            __syncthreads();

            for (int i = tid; i < 1024; i += 256) {
                int r = i >> 4, c = i & 15;
                *(uint4*)(vb + r * 136 + c * 8) =
                    *(const uint4*)(g_v + (size_t)(b * T_ + s0 + r) * HS_ + c * 8);
            }

            #pragma unroll
            for (int i = 0; i < 8; i++) {
                const int row = warp * 8 + i;
                float* prow = sc + row * 68;
                float s1 = prow[lane], s2 = prow[lane + 32];
                float mt = fmaxf(s1, s2);
                #pragma unroll
                for (int o = 16; o; o >>= 1) mt = fmaxf(mt, __shfl_xor_sync(0xffffffffu, mt, o));
                float mn = fmaxf(m_r[i], mt);
                float f = __expf(m_r[i] - mn);
                __half e1h = __float2half_rn(__expf(s1 - mn));
                __half e2h = __float2half_rn(__expf(s2 - mn));
                ph[row * 72 + lane]      = e1h;
                ph[row * 72 + lane + 32] = e2h;
                float sum = __half2float(e1h) + __half2float(e2h);
                #pragma unroll
                for (int o = 16; o; o >>= 1) sum += __shfl_xor_sync(0xffffffffu, sum, o);
                l_r[i] = l_r[i] * f + sum;
                m_r[i] = mn;
                if (lane == 0) f_row[row] = f;
            }
            __syncthreads();

            {
                const float f1 = f_row[band + lr], f2 = f_row[band + lr + 8];
                #pragma unroll
                for (int nt = 0; nt < 8; nt++) {
                    oacc[nt][0] *= f1; oacc[nt][1] *= f1;
                    oacc[nt][2] *= f2; oacc[nt][3] *= f2;
                }
            }

            #pragma unroll
            for (int kk = 0; kk < 4; kk++) {
                unsigned pm[4];
                LDSM_X4(pm[0], pm[1], pm[2], pm[3], aP + kk * 32);
                #pragma unroll
                for (int np = 0; np < 4; np++) {
                    unsigned v0, v1, v2, v3;
                    LDSM_X4_T(v0, v1, v2, v3,
                              bV + (uint32_t)(kk * 16 * 136 + np * 16) * 2);
                    MMA_F16(oacc[np * 2],     pm, v0, v1);
                    MMA_F16(oacc[np * 2 + 1], pm, v2, v3);
                }
            }
            CP_WAIT(0);
            __syncthreads();
        }

        if (lane == 0) {
            #pragma unroll
            for (int i = 0; i < 8; i++) l_row[warp * 8 + i] = l_r[i];
        }
        __syncthreads();

        {
            const float inv1 = 1.f / l_row[band + lr];
            const float inv2 = 1.f / l_row[band + lr + 8];
            const size_t r1 = (size_t)(b * T_ + t0 + band + lr) * HS_;
            const size_t r2 = (size_t)(b * T_ + t0 + band + lr + 8) * HS_;
            #pragma unroll
            for (int nt = 0; nt < 8; nt++) {
                const int col = hf * 64 + nt * 8 + 2 * lc;
                *(float2*)(out + r1 + col) = make_float2(oacc[nt][0] * inv1, oacc[nt][1] * inv1);
                *(float2*)(out + r2 + col) = make_float2(oacc[nt][2] * inv2, oacc[nt][3] * inv2);
            }
        }
    }
}

// ----------------------------------------------------------------------------
extern "C" void kernel_launch(void* const* d_in, const int* in_sizes, int n_in,
                              void* d_out, int out_size)
{
    (void)in_sizes; (void)n_in; (void)out_size;
    const float* x  = (const float*)d_in[0];
    const float* Wk = (const float*)d_in[1];
    const float* Wq = (const float*)d_in[2];
    const float* Wv = (const float*)d_in[3];

    prep_wt<<<dim3(C_ / 32, HS_ / 32, 3), 256>>>(Wk, Wq, Wv);

    cudaFuncSetAttribute(fused_kernel, cudaFuncAttributeMaxDynamicSharedMemorySize, PSMEM);
    fused_kernel<<<512, 256, PSMEM>>>(x, (float*)d_out);
}

// round 12
// speedup vs baseline: 1.1478x; 1.1478x over previous
#include <cuda_runtime.h>
#include <cuda_fp16.h>
#include <cstdint>

#define B_  64
#define T_  256
#define C_  2048
#define HS_ 128
#define M_  (B_ * T_)

// Scratch (no cudaMalloc allowed)
__device__ __half g_k[M_ * HS_];
__device__ __half g_q[M_ * HS_];
__device__ __half g_v[M_ * HS_];
__device__ __half g_wh[3 * HS_ * C_];   // [384][2048] fp16 RNE, K-major
__device__ unsigned g_cnt[B_];          // per-batch proj-tile completion counters

__device__ __forceinline__ void cpa16(void* dst_smem, const void* src_gmem) {
    unsigned d = (unsigned)__cvta_generic_to_shared(dst_smem);
    asm volatile("cp.async.cg.shared.global [%0], [%1], 16;" :: "r"(d), "l"(src_gmem));
}
#define CP_COMMIT  asm volatile("cp.async.commit_group;")
#define CP_WAIT(n) asm volatile("cp.async.wait_group %0;" :: "n"(n))

#define MMA_F16(acc, a, b0, b1)                                                 \
    asm volatile(                                                               \
        "mma.sync.aligned.m16n8k16.row.col.f32.f16.f16.f32 "                    \
        "{%0,%1,%2,%3}, {%4,%5,%6,%7}, {%8,%9}, {%0,%1,%2,%3};"                 \
        : "+f"((acc)[0]), "+f"((acc)[1]), "+f"((acc)[2]), "+f"((acc)[3])        \
        : "r"((a)[0]), "r"((a)[1]), "r"((a)[2]), "r"((a)[3]),                   \
          "r"(b0), "r"(b1))

#define LDSM_X4(r0, r1, r2, r3, addr)                                           \
    asm volatile("ldmatrix.sync.aligned.m8n8.x4.shared.b16 {%0,%1,%2,%3}, [%4];"\
        : "=r"(r0), "=r"(r1), "=r"(r2), "=r"(r3) : "r"(addr))

#define LDSM_X4_T(r0, r1, r2, r3, addr)                                         \
    asm volatile("ldmatrix.sync.aligned.m8n8.x4.trans.shared.b16 {%0,%1,%2,%3}, [%4];"\
        : "=r"(r0), "=r"(r1), "=r"(r2), "=r"(r3) : "r"(addr))

// ----------------------------------------------------------------------------
// Prep: g_wh[p*128 + n][k] = fp16_rn(W_p[k][n]); also zeroes batch counters.
// ----------------------------------------------------------------------------
__global__ void prep_wt(const float* __restrict__ Wk, const float* __restrict__ Wq,
                        const float* __restrict__ Wv)
{
    if (blockIdx.x == 0 && blockIdx.y == 0 && blockIdx.z == 0 && threadIdx.x < B_)
        g_cnt[threadIdx.x] = 0;

    __shared__ float t[32][33];
    const float* W = blockIdx.z == 0 ? Wk : (blockIdx.z == 1 ? Wq : Wv);
    const int k0 = blockIdx.x * 32, n0 = blockIdx.y * 32;
    const int tx = threadIdx.x & 31, ty = threadIdx.x >> 5;
    #pragma unroll
    for (int i = 0; i < 32; i += 8)
        t[ty + i][tx] = W[(size_t)(k0 + ty + i) * HS_ + n0 + tx];
    __syncthreads();
    #pragma unroll
    for (int i = 0; i < 32; i += 8)
        g_wh[((size_t)blockIdx.z * HS_ + n0 + ty + i) * C_ + k0 + tx] =
            __float2half_rn(t[tx][ty + i]);
}

// ----------------------------------------------------------------------------
// Fused proj + attention mega-kernel.
// bids 0..255: proj m-tile (M64 x N384 x K2048). A is fp16 in smem now:
//   LDG fp32 -> cvt f16x2 -> STS.128 (swizzled) -> ldmatrix fragments.
// bids 256..511: attention (unchanged).
// ----------------------------------------------------------------------------
#define NF    384
#define NKT   (C_ / 32)           // 64
#define ASTGB 4096                 // A stage: 64 rows x 64 B (fp16, swizzled)
#define BSTGH (NF * 32)            // B stage halves (24576 B)
#define PSMEM (3 * (ASTGB + BSTGH * 2))   // 86016 B (attn needs 96768 -> use max)

__global__ __launch_bounds__(256, 2) void fused_kernel(const float* __restrict__ x,
                                                       float* __restrict__ out)
{
    extern __shared__ char smraw[];
    const int tid  = threadIdx.x;
    const int warp = tid >> 5, lane = tid & 31;
    const int lr = lane >> 2, lc = lane & 3;
    const int bid = blockIdx.x;

    if (bid < 256) {
        // ==================== PROJ path ====================
        __half* Ah = (__half*)smraw;                       // 3 stages x 4096 B
        __half* Bs = (__half*)(smraw + 3 * ASTGB);         // 3 stages, swizzled
        const uint32_t Ah_u = (uint32_t)__cvta_generic_to_shared(Ah);
        const uint32_t Bs_u = (uint32_t)__cvta_generic_to_shared(Bs);

        const int wm = warp >> 2, wn = warp & 3;           // 2m x 4n
        const int m0 = bid * 64;

        // ---- producer mapping: thread -> x row, 8-float chunk ----
        const int prow = tid >> 2;                         // 0..63
        const int pchunk = (tid & 3) ^ ((prow >> 1) & 3);  // swizzled 16B chunk
        const float* xrow = x + (size_t)(m0 + prow) * C_ + (tid & 3) * 8;
        const uint32_t stsA_off = (uint32_t)(prow * 64 + pchunk * 16);

        // ---- A ldmatrix lane constants ----
        const int arow_l = wm * 32 + (lane & 15);
        const int xsel   = (arow_l >> 1) & 3;
        const int ahi    = lane >> 4;
        const uint32_t aoff[2] = {
            (uint32_t)(arow_l * 64 + ((ahi)     ^ xsel) * 16),   // ks=0
            (uint32_t)(arow_l * 64 + ((2 + ahi) ^ xsel) * 16)    // ks=1
        };

        // ---- B ldmatrix lane constants (unchanged) ----
        const int brow  = wn * 96 + (lane & 15);
        const int bsel  = (brow >> 1) & 3;
        const int bln16 = lane >> 4;

        auto loadB = [&](int s, int j) {
            __half* Bd = Bs + s * BSTGH;
            const int k0 = j * 32;
            #pragma unroll
            for (int i = 0; i < 6; i++) {                  // 1536 x 16B, swizzled
                int c = tid + i * 256, r = c >> 2, cc = c & 3;
                cpa16(Bd + r * 32 + ((cc ^ ((r >> 1) & 3)) * 8),
                      g_wh + (size_t)r * C_ + k0 + cc * 8);
            }
            CP_COMMIT;
        };
        auto ldgA = [&](int j, float4& v0, float4& v1) {
            const float* s = xrow + j * 32;
            v0 = *(const float4*)s;
            v1 = *(const float4*)(s + 4);
        };
        auto stsA = [&](int s, const float4& v0, const float4& v1) {
            __half2 h0 = __floats2half2_rn(v0.x, v0.y);
            __half2 h1 = __floats2half2_rn(v0.z, v0.w);
            __half2 h2 = __floats2half2_rn(v1.x, v1.y);
            __half2 h3 = __floats2half2_rn(v1.z, v1.w);
            uint4 u;
            u.x = *reinterpret_cast<unsigned*>(&h0);
            u.y = *reinterpret_cast<unsigned*>(&h1);
            u.z = *reinterpret_cast<unsigned*>(&h2);
            u.w = *reinterpret_cast<unsigned*>(&h3);
            *(uint4*)((char*)Ah + s * ASTGB + stsA_off) = u;
        };

        // prologue
        loadB(0, 0);
        loadB(1, 1);
        float4 v0, v1;
        ldgA(0, v0, v1);
        stsA(0, v0, v1);
        ldgA(1, v0, v1);

        float acc[2][12][4] = {};

        for (int j = 0; j < NKT; j++) {
            if (j < NKT - 1) { CP_WAIT(1); } else { CP_WAIT(0); }
            __syncthreads();   // B(j) + A(j) visible

            if (j + 2 < NKT) loadB((j + 2) % 3, j + 2);

            const uint32_t Aju = Ah_u + (uint32_t)((j % 3) * ASTGB);
            const uint32_t Bju = Bs_u + (uint32_t)((j % 3) * BSTGH) * 2;

            #pragma unroll
            for (int ks = 0; ks < 2; ks++) {
                unsigned a0[4], a1[4];
                LDSM_X4(a0[0], a0[1], a0[2], a0[3], Aju + aoff[ks]);            // mi=0
                LDSM_X4(a1[0], a1[1], a1[2], a1[3], Aju + 1024 + aoff[ks]);     // mi=1
                const uint32_t chnk = (uint32_t)(((2 * ks + bln16) ^ bsel) * 16);
                #pragma unroll
                for (int pr = 0; pr < 6; pr++) {
                    unsigned b0, b1, b2, b3;
                    LDSM_X4(b0, b1, b2, b3,
                            Bju + (uint32_t)(brow * 64 + pr * 1024) + chnk);
                    MMA_F16(acc[0][2 * pr],     a0, b0, b2);
                    MMA_F16(acc[0][2 * pr + 1], a0, b1, b3);
                    MMA_F16(acc[1][2 * pr],     a1, b0, b2);
                    MMA_F16(acc[1][2 * pr + 1], a1, b1, b3);
                }
            }

            if (j + 1 < NKT) stsA((j + 1) % 3, v0, v1);
            if (j + 2 < NKT) ldgA(j + 2, v0, v1);
        }

        // epilogue: fp16 outputs split across K/Q/V
        __half* const outp[3] = { g_k, g_q, g_v };
        #pragma unroll
        for (int mi = 0; mi < 2; mi++) {
            const int row0 = m0 + wm * 32 + mi * 16 + lr;
            #pragma unroll
            for (int ni = 0; ni < 12; ni++) {
                const int gcol = wn * 96 + ni * 8;
                __half* o = outp[gcol >> 7];
                const int col = (gcol & 127) + 2 * lc;
                __half2 h1 = __floats2half2_rn(acc[mi][ni][0], acc[mi][ni][1]);
                __half2 h2 = __floats2half2_rn(acc[mi][ni][2], acc[mi][ni][3]);
                *(__half2*)(o + (size_t)row0 * HS_ + col)       = h1;
                *(__half2*)(o + (size_t)(row0 + 8) * HS_ + col) = h2;
            }
        }

        __threadfence();
        __syncthreads();
        if (tid == 0) atomicAdd(&g_cnt[bid >> 2], 1u);

    } else {
        // ==================== ATTENTION path ====================
        const int abid = bid - 256;
        const int bt = abid & 3;
        const int b  = abid >> 2;

        if (tid == 0) {
            unsigned v;
            do {
                asm volatile("ld.global.acquire.gpu.b32 %0, [%1];"
                             : "=r"(v) : "l"(g_cnt + b) : "memory");
                if (v < 4) __nanosleep(128);
            } while (v < 4);
        }
        __syncthreads();

        float*  sc    = (float*)smraw;                 // [64][68]
        float*  f_row = sc + 64 * 68;                  // [64]
        float*  l_row = f_row + 64;                    // [64]
        __half* ph    = (__half*)(l_row + 64);         // [64][72]
        __half* kt    = ph + 64 * 72;                  // [64][136]
        __half* q0    = kt + 64 * 136;                 // [64][136]
        __half* q1    = q0 + 64 * 136;                 // [64][136]
        __half* vb    = q1 + 64 * 136;                 // [64][136]
        const uint32_t ph_u = (uint32_t)__cvta_generic_to_shared(ph);
        const uint32_t kt_u = (uint32_t)__cvta_generic_to_shared(kt);
        const uint32_t q0_u = (uint32_t)__cvta_generic_to_shared(q0);
        const uint32_t q1_u = (uint32_t)__cvta_generic_to_shared(q1);
        const uint32_t vb_u = (uint32_t)__cvta_generic_to_shared(vb);

        const int band = (warp & 3) * 16;
        const int hf = warp >> 2;
        const int t0 = bt * 64;
        const float scale = rsqrtf((float)C_);

        const uint32_t aK  = kt_u + (uint32_t)((band + (lane & 15)) * 136 + (lane >> 4) * 8) * 2;
        const uint32_t oQ  = (uint32_t)((hf * 32 + (lane & 7) + (lane >> 4) * 8) * 136
                                        + ((lane >> 3) & 1) * 8) * 2;
        const uint32_t aP  = ph_u + (uint32_t)((band + (lane & 15)) * 72 + (lane >> 4) * 8) * 2;
        const uint32_t bV  = vb_u + (uint32_t)(((lane & 7) + ((lane >> 3) & 1) * 8) * 136
                                               + hf * 64 + (lane >> 4) * 8) * 2;

        #pragma unroll
        for (int i = 0; i < 4; i++) {
            int c = tid + i * 256, r = c >> 4, q = c & 15;
            cpa16(kt + r * 136 + q * 8, g_k + (size_t)(b * T_ + t0 + r) * HS_ + q * 8);
            cpa16(q0 + r * 136 + q * 8, g_q + (size_t)(b * T_ + r) * HS_ + q * 8);
        }
        CP_COMMIT;
        CP_WAIT(0);
        __syncthreads();

        float m_r[8], l_r[8];
        float oacc[8][4] = {};
        #pragma unroll
        for (int i = 0; i < 8; i++) { m_r[i] = -INFINITY; l_r[i] = 0.f; }

        const int n_stiles = bt + 1;
        for (int st = 0; st < n_stiles; st++) {
            const int s0 = st * 64;
            __half* qn = (st & 1) ? q0 : q1;
            const uint32_t qc_u = (st & 1) ? q1_u : q0_u;

            if (st + 1 < n_stiles) {
                #pragma unroll
                for (int i = 0; i < 4; i++) {
                    int c = tid + i * 256, r = c >> 4, q = c & 15;
                    cpa16(qn + r * 136 + q * 8,
                          g_q + (size_t)(b * T_ + s0 + 64 + r) * HS_ + q * 8);
                }
            }
            CP_COMMIT;

            float sacc[4][4] = {};
            #pragma unroll
            for (int kk = 0; kk < 8; kk++) {
                unsigned a[4];
                LDSM_X4(a[0], a[1], a[2], a[3], aK + kk * 32);
                unsigned e0, e1, e2, e3, r0, r1, r2, r3;
                LDSM_X4(e0, e1, e2, e3, qc_u + oQ + kk * 32);
                LDSM_X4(r0, r1, r2, r3, qc_u + oQ + 16 * 136 * 2 + kk * 32);
                MMA_F16(sacc[0], a, e0, e1);
                MMA_F16(sacc[1], a, e2, e3);
                MMA_F16(sacc[2], a, r0, r1);
                MMA_F16(sacc[3], a, r2, r3);
            }
            const bool diag = (st == bt);
            #pragma unroll
            for (int nt = 0; nt < 4; nt++) {
                const int row = band + lr, col = hf * 32 + nt * 8 + 2 * lc;
                const int tg = t0 + row, sg = s0 + col;
                sc[row * 68 + col]           = (!diag || sg     <= tg)     ? sacc[nt][0] * scale : -INFINITY;
                sc[row * 68 + col + 1]       = (!diag || sg + 1 <= tg)     ? sacc[nt][1] * scale : -INFINITY;
                sc[(row + 8) * 68 + col]     = (!diag || sg     <= tg + 8) ? sacc[nt][2] * scale : -INFINITY;
                sc[(row + 8) * 68 + col + 1] = (!diag || sg + 1 <= tg + 8) ? sacc[nt][3] * scale : -INFINITY;
            }
            __syncthreads();

            for (int i = tid; i < 1024; i += 256) {
                int r = i >> 4, c = i & 15;
                *(uint4*)(vb + r * 136 + c * 8) =
                    *(const uint4*)(g_v + (size_t)(b * T_ + s0 + r) * HS_ + c * 8);
            }

            #pragma unroll
            for (int i = 0; i < 8; i++) {
                const int row = warp * 8 + i;
                float* prow = sc + row * 68;
                float s1 = prow[lane], s2 = prow[lane + 32];
                float mt = fmaxf(s1, s2);
                #pragma unroll
                for (int o = 16; o; o >>= 1) mt = fmaxf(mt, __shfl_xor_sync(0xffffffffu, mt, o));
                float mn = fmaxf(m_r[i], mt);
                float f = __expf(m_r[i] - mn);
                __half e1h = __float2half_rn(__expf(s1 - mn));
                __half e2h = __float2half_rn(__expf(s2 - mn));
                ph[row * 72 + lane]      = e1h;
                ph[row * 72 + lane + 32] = e2h;
                float sum = __half2float(e1h) + __half2float(e2h);
                #pragma unroll
                for (int o = 16; o; o >>= 1) sum += __shfl_xor_sync(0xffffffffu, sum, o);
                l_r[i] = l_r[i] * f + sum;
                m_r[i] = mn;
                if (lane == 0) f_row[row] = f;
            }
            __syncthreads();

            {
                const float f1 = f_row[band + lr], f2 = f_row[band + lr + 8];
                #pragma unroll
                for (int nt = 0; nt < 8; nt++) {
                    oacc[nt][0] *= f1; oacc[nt][1] *= f1;
                    oacc[nt][2] *= f2; oacc[nt][3] *= f2;
                }
            }

            #pragma unroll
            for (int kk = 0; kk < 4; kk++) {
                unsigned pm[4];
                LDSM_X4(pm[0], pm[1], pm[2], pm[3], aP + kk * 32);
                #pragma unroll
                for (int np = 0; np < 4; np++) {
                    unsigned w0, w1, w2, w3;
                    LDSM_X4_T(w0, w1, w2, w3,
                              bV + (uint32_t)(kk * 16 * 136 + np * 16) * 2);
                    MMA_F16(oacc[np * 2],     pm, w0, w1);
                    MMA_F16(oacc[np * 2 + 1], pm, w2, w3);
                }
            }
            CP_WAIT(0);
            __syncthreads();
        }

        if (lane == 0) {
            #pragma unroll
            for (int i = 0; i < 8; i++) l_row[warp * 8 + i] = l_r[i];
        }
        __syncthreads();

        {
            const float inv1 = 1.f / l_row[band + lr];
            const float inv2 = 1.f / l_row[band + lr + 8];
            const size_t r1 = (size_t)(b * T_ + t0 + band + lr) * HS_;
            const size_t r2 = (size_t)(b * T_ + t0 + band + lr + 8) * HS_;
            #pragma unroll
            for (int nt = 0; nt < 8; nt++) {
                const int col = hf * 64 + nt * 8 + 2 * lc;
                *(float2*)(out + r1 + col) = make_float2(oacc[nt][0] * inv1, oacc[nt][1] * inv1);
                *(float2*)(out + r2 + col) = make_float2(oacc[nt][2] * inv2, oacc[nt][3] * inv2);
            }
        }
    }
}

// ----------------------------------------------------------------------------
extern "C" void kernel_launch(void* const* d_in, const int* in_sizes, int n_in,
                              void* d_out, int out_size)
{
    (void)in_sizes; (void)n_in; (void)out_size;
    const float* x  = (const float*)d_in[0];
    const float* Wk = (const float*)d_in[1];
    const float* Wq = (const float*)d_in[2];
    const float* Wv = (const float*)d_in[3];

    prep_wt<<<dim3(C_ / 32, HS_ / 32, 3), 256>>>(Wk, Wq, Wv);

    const int fsm = 96768;   // max(proj 86016, attn 96768)
    cudaFuncSetAttribute(fused_kernel, cudaFuncAttributeMaxDynamicSharedMemorySize, fsm);
    fused_kernel<<<512, 256, fsm>>>(x, (float*)d_out);
}